// round 1
// baseline (speedup 1.0000x reference)
#include <cuda_runtime.h>
#include <math.h>

// Problem constants
#define Bn    128
#define HIDD  64
#define INDIM 2
#define CX    66          // IN_DIM + HID channels per part
#define NN    1024        // graph nodes (= GEMM K and N)
#define MROWS (Bn * CX)   // 8448 rows in the big GEMMs
#define KPROJ 330         // 5 parts * 66

// -------- scratch (device globals: allocation-free) --------
__device__ float g_X [MROWS * NN];   // X  (or Xc in pass 2)
__device__ float g_P1[MROWS * NN];   // X @ A0^T
__device__ float g_P2[MROWS * NN];   // 2*X1*A0^T - X
__device__ float g_P3[MROWS * NN];   // X @ A1^T
__device__ float g_P4[MROWS * NN];   // 2*X3*A1^T - X
__device__ float g_RU[Bn * 2 * HIDD * NN];   // sigmoid gates (B,128,N)

// ============================================================
// GEMM (NT): C[m,j] = alpha * sum_k X[m,k]*Adj[j,k] + beta*Cadd[m,j]
// M = 8448, N = 1024, K = 1024 (all tile-exact: 66 x 8 blocks of 128x128)
// ============================================================
__global__ void __launch_bounds__(256, 2)
gemm_nt_kernel(const float* __restrict__ X, const float* __restrict__ Adj,
               const float* __restrict__ Cadd, float* __restrict__ Cout,
               float alpha, float beta)
{
    __shared__ float As[8][132];   // [k][m], padded to kill STS conflicts
    __shared__ float Bs[8][132];   // [k][n]

    const int tid = threadIdx.x;
    const int bm  = blockIdx.y * 128;
    const int bn  = blockIdx.x * 128;

    // loaders: thread -> (row, k-quad)
    const int lr = tid >> 1;           // 0..127
    const int lk = (tid & 1) * 4;      // 0 or 4
    const float* Xg = X   + (size_t)(bm + lr) * NN + lk;
    const float* Bg = Adj + (size_t)(bn + lr) * NN + lk;

    // compute mapping: 16x16 threads, 8x8 microtile
    const int ty = tid >> 4;           // row group
    const int tx = tid & 15;           // col group
    const int ty8 = ty * 8;
    const int tx8 = tx * 8;

    float acc[8][8];
#pragma unroll
    for (int i = 0; i < 8; i++)
#pragma unroll
        for (int j = 0; j < 8; j++) acc[i][j] = 0.0f;

    for (int kt = 0; kt < NN; kt += 8) {
        float4 av = *(const float4*)(Xg + kt);
        float4 bv = *(const float4*)(Bg + kt);
        As[lk + 0][lr] = av.x; As[lk + 1][lr] = av.y;
        As[lk + 2][lr] = av.z; As[lk + 3][lr] = av.w;
        Bs[lk + 0][lr] = bv.x; Bs[lk + 1][lr] = bv.y;
        Bs[lk + 2][lr] = bv.z; Bs[lk + 3][lr] = bv.w;
        __syncthreads();

#pragma unroll
        for (int k = 0; k < 8; k++) {
            float a[8], b[8];
            *(float4*)&a[0] = *(const float4*)&As[k][ty8];
            *(float4*)&a[4] = *(const float4*)&As[k][ty8 + 4];
            *(float4*)&b[0] = *(const float4*)&Bs[k][tx8];
            *(float4*)&b[4] = *(const float4*)&Bs[k][tx8 + 4];
#pragma unroll
            for (int i = 0; i < 8; i++)
#pragma unroll
                for (int j = 0; j < 8; j++)
                    acc[i][j] = fmaf(a[i], b[j], acc[i][j]);
        }
        __syncthreads();
    }

#pragma unroll
    for (int i = 0; i < 8; i++) {
        const int row = bm + ty8 + i;
        float* outp = Cout + (size_t)row * NN + bn + tx8;
        if (beta != 0.0f) {
            const float* cp = Cadd + (size_t)row * NN + bn + tx8;
#pragma unroll
            for (int j = 0; j < 8; j++)
                acc[i][j] = alpha * acc[i][j] + beta * cp[j];
        } else {
#pragma unroll
            for (int j = 0; j < 8; j++) acc[i][j] *= alpha;
        }
        *(float4*)(outp)     = *(float4*)&acc[i][0];
        *(float4*)(outp + 4) = *(float4*)&acc[i][4];
    }
}

// ============================================================
// Projection over the 5 parts + fused epilogue.
// mode 0: RUout = sigmoid(W @ H + bias)         (O tile via grid.y, O=128)
// mode 1: out   = u*hx + (1-u)*tanh(W @ H + b)  (O=64, u from g_RU)
// grid: (NN/128, O/64, B), block 256
// ============================================================
__global__ void __launch_bounds__(256)
proj_kernel(const float* __restrict__ W, const float* __restrict__ bias,
            const float* __restrict__ p0, const float* __restrict__ p1,
            const float* __restrict__ p2, const float* __restrict__ p3,
            const float* __restrict__ p4,
            const float* __restrict__ RU, const float* __restrict__ hx,
            float* __restrict__ outp, int mode)
{
    __shared__ float Ws[16][64];    // [k][o]
    __shared__ float Hs[16][128];   // [k][n]

    const int tid = threadIdx.x;
    const int b   = blockIdx.z;
    const int bn  = blockIdx.x * 128;
    const int bo  = blockIdx.y * 64;

    // loaders
    const int hk = tid >> 4;            // 0..15  (H k-row)
    const int hn = (tid & 15) * 8;      // H col base
    const int wo = tid & 63;            // W o
    const int wk = (tid >> 6) * 4;      // W k base (4 each)

    // compute mapping: 4(o) x 8(n) microtile
    const int ty4 = (tid >> 4) * 4;
    const int tx8 = (tid & 15) * 8;

    float acc[4][8];
#pragma unroll
    for (int i = 0; i < 4; i++)
#pragma unroll
        for (int j = 0; j < 8; j++) acc[i][j] = 0.0f;

    for (int kt = 0; kt < 336; kt += 16) {
        // H tile
        {
            const int k = kt + hk;
            float4 v0 = make_float4(0.f, 0.f, 0.f, 0.f);
            float4 v1 = v0;
            if (k < KPROJ) {
                const int p = k / 66;
                const int c = k - p * 66;
                const float* src = p0;
                if (p == 1) src = p1;
                else if (p == 2) src = p2;
                else if (p == 3) src = p3;
                else if (p == 4) src = p4;
                const float* g = src + ((size_t)b * CX + c) * NN + bn + hn;
                v0 = *(const float4*)g;
                v1 = *(const float4*)(g + 4);
            }
            *(float4*)&Hs[hk][hn]     = v0;
            *(float4*)&Hs[hk][hn + 4] = v1;
        }
        // W tile
#pragma unroll
        for (int i = 0; i < 4; i++) {
            const int k = kt + wk + i;
            Ws[wk + i][wo] = (k < KPROJ)
                ? W[(size_t)(bo + wo) * KPROJ + k] : 0.0f;
        }
        __syncthreads();

#pragma unroll
        for (int k = 0; k < 16; k++) {
            float a[4], bb[8];
            *(float4*)&a[0]  = *(const float4*)&Ws[k][ty4];
            *(float4*)&bb[0] = *(const float4*)&Hs[k][tx8];
            *(float4*)&bb[4] = *(const float4*)&Hs[k][tx8 + 4];
#pragma unroll
            for (int i = 0; i < 4; i++)
#pragma unroll
                for (int j = 0; j < 8; j++)
                    acc[i][j] = fmaf(a[i], bb[j], acc[i][j]);
        }
        __syncthreads();
    }

#pragma unroll
    for (int i = 0; i < 4; i++) {
        const int o = bo + ty4 + i;
        const float bv = bias[o];
        float res[8];
        float* dst;
        if (mode == 0) {
#pragma unroll
            for (int j = 0; j < 8; j++)
                res[j] = 1.0f / (1.0f + expf(-(acc[i][j] + bv)));
            dst = outp + ((size_t)b * 128 + o) * NN + bn + tx8;
        } else {
            const float* urow = RU + ((size_t)b * 128 + 64 + o) * NN + bn + tx8;
            const float* hrow = hx + ((size_t)b * HIDD + o) * NN + bn + tx8;
#pragma unroll
            for (int j = 0; j < 8; j++) {
                const float cc = tanhf(acc[i][j] + bv);
                const float u  = urow[j];
                res[j] = u * hrow[j] + (1.0f - u) * cc;
            }
            dst = outp + ((size_t)b * HIDD + o) * NN + bn + tx8;
        }
        *(float4*)(dst)     = *(float4*)&res[0];
        *(float4*)(dst + 4) = *(float4*)&res[4];
    }
}

// ============================================================
// pack1: X = concat([inputs, hx], channel)    (vectorized float4)
// pack2: Xc = concat([inputs, r*hx]), r = RU[:, :64, :]
// ============================================================
__global__ void pack1_kernel(const float* __restrict__ inputs,
                             const float* __restrict__ hx,
                             float* __restrict__ X)
{
    const int idx = blockIdx.x * blockDim.x + threadIdx.x;  // over MROWS*256 float4
    if (idx >= MROWS * 256) return;
    const int n4 = idx & 255;
    const int t  = idx >> 8;
    const int c  = t % CX;
    const int b  = t / CX;
    float4 v;
    if (c < INDIM)
        v = ((const float4*)inputs)[((size_t)b * INDIM + c) * 256 + n4];
    else
        v = ((const float4*)hx)[((size_t)b * HIDD + (c - INDIM)) * 256 + n4];
    ((float4*)X)[idx] = v;
}

__global__ void pack2_kernel(const float* __restrict__ inputs,
                             const float* __restrict__ hx,
                             const float* __restrict__ RU,
                             float* __restrict__ Xc)
{
    const int idx = blockIdx.x * blockDim.x + threadIdx.x;
    if (idx >= MROWS * 256) return;
    const int n4 = idx & 255;
    const int t  = idx >> 8;
    const int c  = t % CX;
    const int b  = t / CX;
    float4 v;
    if (c < INDIM) {
        v = ((const float4*)inputs)[((size_t)b * INDIM + c) * 256 + n4];
    } else {
        const int cc = c - INDIM;
        float4 r = ((const float4*)RU)[((size_t)b * 128 + cc) * 256 + n4];
        float4 h = ((const float4*)hx)[((size_t)b * HIDD + cc) * 256 + n4];
        v.x = r.x * h.x; v.y = r.y * h.y; v.z = r.z * h.z; v.w = r.w * h.w;
    }
    ((float4*)Xc)[idx] = v;
}

// ============================================================
extern "C" void kernel_launch(void* const* d_in, const int* in_sizes, int n_in,
                              void* d_out, int out_size)
{
    const float* inputs = (const float*)d_in[0];
    const float* hx     = (const float*)d_in[1];
    const float* A0     = (const float*)d_in[2];
    const float* A1     = (const float*)d_in[3];
    const float* W_ru   = (const float*)d_in[4];
    const float* b_ru   = (const float*)d_in[5];
    const float* W_C    = (const float*)d_in[6];
    const float* b_C    = (const float*)d_in[7];
    float* out = (float*)d_out;

    float *gX, *gP1, *gP2, *gP3, *gP4, *gRU;
    cudaGetSymbolAddress((void**)&gX,  g_X);
    cudaGetSymbolAddress((void**)&gP1, g_P1);
    cudaGetSymbolAddress((void**)&gP2, g_P2);
    cudaGetSymbolAddress((void**)&gP3, g_P3);
    cudaGetSymbolAddress((void**)&gP4, g_P4);
    cudaGetSymbolAddress((void**)&gRU, g_RU);

    const dim3 ggrid(NN / 128, MROWS / 128);  // (8, 66)
    const int packBlocks = (MROWS * 256 + 255) / 256;

    // ---------- pass 1: ru gates ----------
    pack1_kernel<<<packBlocks, 256>>>(inputs, hx, gX);
    gemm_nt_kernel<<<ggrid, 256>>>(gX,  A0, nullptr, gP1, 1.0f,  0.0f);
    gemm_nt_kernel<<<ggrid, 256>>>(gP1, A0, gX,      gP2, 2.0f, -1.0f);
    gemm_nt_kernel<<<ggrid, 256>>>(gX,  A1, nullptr, gP3, 1.0f,  0.0f);
    gemm_nt_kernel<<<ggrid, 256>>>(gP3, A1, gX,      gP4, 2.0f, -1.0f);
    proj_kernel<<<dim3(8, 2, Bn), 256>>>(W_ru, b_ru, gX, gP1, gP2, gP3, gP4,
                                         nullptr, nullptr, gRU, 0);

    // ---------- pass 2: candidate + output ----------
    pack2_kernel<<<packBlocks, 256>>>(inputs, hx, gRU, gX);
    gemm_nt_kernel<<<ggrid, 256>>>(gX,  A0, nullptr, gP1, 1.0f,  0.0f);
    gemm_nt_kernel<<<ggrid, 256>>>(gP1, A0, gX,      gP2, 2.0f, -1.0f);
    gemm_nt_kernel<<<ggrid, 256>>>(gX,  A1, nullptr, gP3, 1.0f,  0.0f);
    gemm_nt_kernel<<<ggrid, 256>>>(gP3, A1, gX,      gP4, 2.0f, -1.0f);
    proj_kernel<<<dim3(8, 1, Bn), 256>>>(W_C, b_C, gX, gP1, gP2, gP3, gP4,
                                         gRU, hx, out, 1);
}

// round 3
// speedup vs baseline: 2.3364x; 2.3364x over previous
#include <cuda_runtime.h>
#include <cuda_bf16.h>
#include <math.h>
#include <stdint.h>

// Problem constants
#define Bn    128
#define HIDD  64
#define INDIM 2
#define CX    66
#define NN    1024
#define MROWS (Bn * CX)       // 8448
#define KPROJ 330
#define KW    2048            // hi|lo packed width per row

// ---------------- scratch (device globals) ----------------
__device__ __nv_bfloat16 g_X [MROWS * KW];
__device__ __nv_bfloat16 g_P1[MROWS * KW];
__device__ __nv_bfloat16 g_P2[MROWS * KW];
__device__ __nv_bfloat16 g_P3[MROWS * KW];
__device__ __nv_bfloat16 g_P4[MROWS * KW];
__device__ __nv_bfloat16 g_A [2 * NN * KW];          // A0,A1 split hi|lo
__device__ float         g_RU[Bn * 2 * HIDD * NN];   // sigmoid gates fp32

// ---------------- PTX helpers (base-ISA only: no tcgen05) ----------------
__device__ __forceinline__ uint32_t smem_u32(const void* p) {
    uint32_t a;
    asm("{ .reg .u64 t; cvta.to.shared.u64 t, %1; cvt.u32.u64 %0, t; }" : "=r"(a) : "l"(p));
    return a;
}
__device__ __forceinline__ void cp16(uint32_t dst, const void* src) {
    asm volatile("cp.async.cg.shared.global [%0], [%1], 16;" :: "r"(dst), "l"(src) : "memory");
}
__device__ __forceinline__ void ldm_x4(uint32_t* r, uint32_t a) {
    asm volatile("ldmatrix.sync.aligned.m8n8.x4.shared.b16 {%0,%1,%2,%3}, [%4];"
                 : "=r"(r[0]), "=r"(r[1]), "=r"(r[2]), "=r"(r[3]) : "r"(a));
}
__device__ __forceinline__ void mma16816(float* c, const uint32_t* a, const uint32_t* b) {
    asm volatile("mma.sync.aligned.m16n8k16.row.col.f32.bf16.bf16.f32 "
                 "{%0,%1,%2,%3},{%4,%5,%6,%7},{%8,%9},{%0,%1,%2,%3};"
                 : "+f"(c[0]), "+f"(c[1]), "+f"(c[2]), "+f"(c[3])
                 : "r"(a[0]), "r"(a[1]), "r"(a[2]), "r"(a[3]), "r"(b[0]), "r"(b[1]));
}

// ============================================================
// Tensor GEMM via mma.sync (HMMA):
//   D[m,n] = sum over 3 segments of Xseg[m,k]*Aseg[n,k]  (K=3072)
//   Out(hi|lo bf16) = split( doBeta ? 2*D - X0 : D )
// CTA tile 128x128, 8 warps (4m x 2n), warp tile 32x64, k-tile 64.
// ============================================================
#define MB 128
#define NB 128
#define KTILE 64
#define NT 48                     // 3 segments * 16 k-tiles
#define ABYTES (MB * KTILE * 2)   // 16384 per operand per buffer
#define SM_TOT (4 * ABYTES)       // 65536

__global__ void __launch_bounds__(256, 2)
mma_gemm(const __nv_bfloat16* __restrict__ Xin,
         const __nv_bfloat16* __restrict__ Ain,
         const __nv_bfloat16* __restrict__ X0,
         __nv_bfloat16* __restrict__ Out,
         int doBeta)
{
    extern __shared__ char smem[];
    const uint32_t sb = smem_u32(smem);
    const int tid  = threadIdx.x;
    const int lane = tid & 31;
    const int wid  = tid >> 5;
    const int wm   = wid & 3;          // 0..3  (m)
    const int wn   = wid >> 2;         // 0..1  (n)
    const int bm   = blockIdx.y * MB;
    const int bn   = blockIdx.x * NB;

    const uint32_t sA[2] = { sb,              sb + 2 * ABYTES };
    const uint32_t sB[2] = { sb + ABYTES,     sb + 3 * ABYTES };

    float acc[2][8][4];
#pragma unroll
    for (int t2 = 0; t2 < 2; t2++)
#pragma unroll
        for (int j = 0; j < 8; j++)
#pragma unroll
            for (int e = 0; e < 4; e++) acc[t2][j][e] = 0.0f;

    // loader mapping: 1024 16B-chunks per operand, 4 per thread
    const int lrow = tid >> 1;                 // reused below per j
    (void)lrow;

    auto fill = [&](int t) {
        const int s    = t >> 4;               // segment 0,1,2
        const int kt   = (t & 15) * 64;
        const int xoff = (s == 1) ? 1024 : 0;
        const int aoff = (s == 2) ? 1024 : 0;
        const uint32_t sa = sA[t & 1], sbuf = sB[t & 1];
#pragma unroll
        for (int j = 0; j < 4; j++) {
            const int u = tid + j * 256;
            const int row = u >> 3, ch = u & 7;
            cp16(sa + row * 128 + ((ch ^ (row & 7)) * 16),
                 Xin + (size_t)(bm + row) * KW + xoff + kt + ch * 8);
        }
#pragma unroll
        for (int j = 0; j < 4; j++) {
            const int u = tid + j * 256;
            const int row = u >> 3, ch = u & 7;
            cp16(sbuf + row * 128 + ((ch ^ (row & 7)) * 16),
                 Ain + (size_t)(bn + row) * KW + aoff + kt + ch * 8);
        }
        asm volatile("cp.async.commit_group;" ::: "memory");
    };

    // ldmatrix lane-dependent row indices (within CTA tile)
    const int arow_l = (lane & 15);            // A: row within m16
    const int ach_l  = (lane >> 4);            // A: k-chunk select (0/1)
    const int bgrp   = lane >> 3;
    const int brow_l = (lane & 7) + ((bgrp >> 1) << 3);  // B: row within n16
    const int bch_l  = (bgrp & 1);             // B: k-chunk select

    fill(0);

    for (int t = 0; t < NT; t++) {
        if (t + 1 < NT) {
            fill(t + 1);
            asm volatile("cp.async.wait_group 1;" ::: "memory");
        } else {
            asm volatile("cp.async.wait_group 0;" ::: "memory");
        }
        __syncthreads();

        const uint32_t sa = sA[t & 1], sbuf = sB[t & 1];
#pragma unroll
        for (int ks = 0; ks < 4; ks++) {
            uint32_t afr[2][4];
#pragma unroll
            for (int t2 = 0; t2 < 2; t2++) {
                const int row = wm * 32 + t2 * 16 + arow_l;
                const int ch  = 2 * ks + ach_l;
                ldm_x4(afr[t2], sa + row * 128 + ((ch ^ (row & 7)) * 16));
            }
            uint32_t bfr[4][4];
#pragma unroll
            for (int tn = 0; tn < 4; tn++) {
                const int row = wn * 64 + tn * 16 + brow_l;
                const int ch  = 2 * ks + bch_l;
                ldm_x4(bfr[tn], sbuf + row * 128 + ((ch ^ (row & 7)) * 16));
            }
#pragma unroll
            for (int t2 = 0; t2 < 2; t2++)
#pragma unroll
                for (int j = 0; j < 8; j++)
                    mma16816(acc[t2][j], afr[t2], &bfr[j >> 1][(j & 1) * 2]);
        }
        __syncthreads();
    }

    // ---- epilogue: (optional 2*D - X0), split to bf16 hi|lo ----
    const int g = lane >> 2;
    const int c2 = (lane & 3) * 2;
#pragma unroll
    for (int t2 = 0; t2 < 2; t2++) {
#pragma unroll
        for (int j = 0; j < 8; j++) {
            const int col = bn + wn * 64 + j * 8 + c2;
#pragma unroll
            for (int half = 0; half < 2; half++) {
                const int row = bm + wm * 32 + t2 * 16 + g + half * 8;
                const size_t base = (size_t)row * KW + col;
                float v0 = acc[t2][j][half * 2 + 0];
                float v1 = acc[t2][j][half * 2 + 1];
                if (doBeta) {
                    union { uint32_t u; __nv_bfloat16 h[2]; } Hh, Hl;
                    Hh.u = *(const uint32_t*)(X0 + base);
                    Hl.u = *(const uint32_t*)(X0 + base + 1024);
                    v0 = 2.0f * v0 - (__bfloat162float(Hh.h[0]) + __bfloat162float(Hl.h[0]));
                    v1 = 2.0f * v1 - (__bfloat162float(Hh.h[1]) + __bfloat162float(Hl.h[1]));
                }
                union { uint32_t u; __nv_bfloat16 h[2]; } Oh, Ol;
                Oh.h[0] = __float2bfloat16(v0);
                Oh.h[1] = __float2bfloat16(v1);
                Ol.h[0] = __float2bfloat16(v0 - __bfloat162float(Oh.h[0]));
                Ol.h[1] = __float2bfloat16(v1 - __bfloat162float(Oh.h[1]));
                *(uint32_t*)(Out + base)        = Oh.u;
                *(uint32_t*)(Out + base + 1024) = Ol.u;
            }
        }
    }
}

// ============================================================
// Projection (SIMT) reading bf16 hi/lo parts.
// mode 0: RU = sigmoid(W@H + b)   grid (8, 2, 128)
// mode 1: out = u*hx + (1-u)*tanh(W@H + b)   grid (8, 1, 128)
// ============================================================
__global__ void __launch_bounds__(256)
proj_kernel(const float* __restrict__ W, const float* __restrict__ bias,
            const __nv_bfloat16* __restrict__ p0, const __nv_bfloat16* __restrict__ p1,
            const __nv_bfloat16* __restrict__ p2, const __nv_bfloat16* __restrict__ p3,
            const __nv_bfloat16* __restrict__ p4,
            const float* __restrict__ RU, const float* __restrict__ hx,
            float* __restrict__ outp, int mode)
{
    __shared__ float Ws[16][64];
    __shared__ float Hs[16][128];

    const int tid = threadIdx.x;
    const int b   = blockIdx.z;
    const int bnn = blockIdx.x * 128;
    const int bo  = blockIdx.y * 64;

    const int hk = tid >> 4;
    const int hn = (tid & 15) * 8;
    const int wo = tid & 63;
    const int wk = (tid >> 6) * 4;
    const int ty4 = (tid >> 4) * 4;
    const int tx8 = (tid & 15) * 8;

    float acc[4][8];
#pragma unroll
    for (int i = 0; i < 4; i++)
#pragma unroll
        for (int j = 0; j < 8; j++) acc[i][j] = 0.0f;

    for (int kt = 0; kt < 336; kt += 16) {
        {
            const int k = kt + hk;
            float vv[8];
#pragma unroll
            for (int j = 0; j < 8; j++) vv[j] = 0.0f;
            if (k < KPROJ) {
                const int p = k / 66;
                const int c = k - p * 66;
                const __nv_bfloat16* src = p0;
                if (p == 1) src = p1;
                else if (p == 2) src = p2;
                else if (p == 3) src = p3;
                else if (p == 4) src = p4;
                const __nv_bfloat16* gp = src + ((size_t)b * CX + c) * KW + bnn + hn;
                union { uint4 u; __nv_bfloat16 h[8]; } Hh, Hl;
                Hh.u = *(const uint4*)(gp);
                Hl.u = *(const uint4*)(gp + 1024);
#pragma unroll
                for (int j = 0; j < 8; j++)
                    vv[j] = __bfloat162float(Hh.h[j]) + __bfloat162float(Hl.h[j]);
            }
#pragma unroll
            for (int j = 0; j < 8; j++) Hs[hk][hn + j] = vv[j];
        }
#pragma unroll
        for (int i = 0; i < 4; i++) {
            const int k = kt + wk + i;
            Ws[wk + i][wo] = (k < KPROJ) ? W[(size_t)(bo + wo) * KPROJ + k] : 0.0f;
        }
        __syncthreads();

#pragma unroll
        for (int k = 0; k < 16; k++) {
            float a[4], bb[8];
            *(float4*)&a[0]  = *(const float4*)&Ws[k][ty4];
            *(float4*)&bb[0] = *(const float4*)&Hs[k][tx8];
            *(float4*)&bb[4] = *(const float4*)&Hs[k][tx8 + 4];
#pragma unroll
            for (int i = 0; i < 4; i++)
#pragma unroll
                for (int j = 0; j < 8; j++)
                    acc[i][j] = fmaf(a[i], bb[j], acc[i][j]);
        }
        __syncthreads();
    }

#pragma unroll
    for (int i = 0; i < 4; i++) {
        const int o = bo + ty4 + i;
        const float bv = bias[o];
        float res[8];
        float* dst;
        if (mode == 0) {
#pragma unroll
            for (int j = 0; j < 8; j++)
                res[j] = 1.0f / (1.0f + expf(-(acc[i][j] + bv)));
            dst = outp + ((size_t)b * 128 + o) * NN + bnn + tx8;
        } else {
            const float* urow = RU + ((size_t)b * 128 + 64 + o) * NN + bnn + tx8;
            const float* hrow = hx + ((size_t)b * HIDD + o) * NN + bnn + tx8;
#pragma unroll
            for (int j = 0; j < 8; j++) {
                const float cc = tanhf(acc[i][j] + bv);
                const float u  = urow[j];
                res[j] = u * hrow[j] + (1.0f - u) * cc;
            }
            dst = outp + ((size_t)b * HIDD + o) * NN + bnn + tx8;
        }
        *(float4*)(dst)     = *(float4*)&res[0];
        *(float4*)(dst + 4) = *(float4*)&res[4];
    }
}

// ============================================================
// split / pack kernels (fp32 -> bf16 hi|lo)
// ============================================================
__device__ __forceinline__ void split4(const float4 v, __nv_bfloat16* hi4, __nv_bfloat16* lo4) {
    const float f[4] = { v.x, v.y, v.z, v.w };
#pragma unroll
    for (int e = 0; e < 4; e++) {
        const __nv_bfloat16 h = __float2bfloat16(f[e]);
        hi4[e] = h;
        lo4[e] = __float2bfloat16(f[e] - __bfloat162float(h));
    }
}

__global__ void splitA_kernel(const float* __restrict__ A0, const float* __restrict__ A1,
                              __nv_bfloat16* __restrict__ Aout)
{
    const int idx = blockIdx.x * blockDim.x + threadIdx.x;   // over 2*1024*256
    if (idx >= 2 * NN * 256) return;
    const int adj = idx >> 18;
    const int r   = idx & ((1 << 18) - 1);
    const int row = r >> 8;
    const int n4  = r & 255;
    const float4 v = ((const float4*)(adj ? A1 : A0))[(size_t)row * 256 + n4];
    union { uint2 u; __nv_bfloat16 h[4]; } H, L;
    split4(v, H.h, L.h);
    __nv_bfloat16* dst = Aout + (size_t)adj * NN * KW + (size_t)row * KW + n4 * 4;
    *(uint2*)(dst)        = H.u;
    *(uint2*)(dst + 1024) = L.u;
}

__global__ void pack1_kernel(const float* __restrict__ inputs, const float* __restrict__ hx,
                             __nv_bfloat16* __restrict__ X)
{
    const int idx = blockIdx.x * blockDim.x + threadIdx.x;   // over MROWS*256
    if (idx >= MROWS * 256) return;
    const int n4 = idx & 255;
    const int t  = idx >> 8;
    const int c  = t % CX;
    const int b  = t / CX;
    float4 v;
    if (c < INDIM)
        v = ((const float4*)inputs)[((size_t)b * INDIM + c) * 256 + n4];
    else
        v = ((const float4*)hx)[((size_t)b * HIDD + (c - INDIM)) * 256 + n4];
    union { uint2 u; __nv_bfloat16 h[4]; } H, L;
    split4(v, H.h, L.h);
    __nv_bfloat16* dst = X + (size_t)t * KW + n4 * 4;
    *(uint2*)(dst)        = H.u;
    *(uint2*)(dst + 1024) = L.u;
}

__global__ void pack2_kernel(const float* __restrict__ inputs, const float* __restrict__ hx,
                             const float* __restrict__ RU, __nv_bfloat16* __restrict__ X)
{
    const int idx = blockIdx.x * blockDim.x + threadIdx.x;
    if (idx >= MROWS * 256) return;
    const int n4 = idx & 255;
    const int t  = idx >> 8;
    const int c  = t % CX;
    const int b  = t / CX;
    float4 v;
    if (c < INDIM) {
        v = ((const float4*)inputs)[((size_t)b * INDIM + c) * 256 + n4];
    } else {
        const int cc = c - INDIM;
        const float4 r = ((const float4*)RU)[((size_t)b * 128 + cc) * 256 + n4];
        const float4 h = ((const float4*)hx)[((size_t)b * HIDD + cc) * 256 + n4];
        v.x = r.x * h.x; v.y = r.y * h.y; v.z = r.z * h.z; v.w = r.w * h.w;
    }
    union { uint2 u; __nv_bfloat16 h[4]; } H, L;
    split4(v, H.h, L.h);
    __nv_bfloat16* dst = X + (size_t)t * KW + n4 * 4;
    *(uint2*)(dst)        = H.u;
    *(uint2*)(dst + 1024) = L.u;
}

// ============================================================
extern "C" void kernel_launch(void* const* d_in, const int* in_sizes, int n_in,
                              void* d_out, int out_size)
{
    const float* inputs = (const float*)d_in[0];
    const float* hx     = (const float*)d_in[1];
    const float* A0     = (const float*)d_in[2];
    const float* A1     = (const float*)d_in[3];
    const float* W_ru   = (const float*)d_in[4];
    const float* b_ru   = (const float*)d_in[5];
    const float* W_C    = (const float*)d_in[6];
    const float* b_C    = (const float*)d_in[7];
    float* out = (float*)d_out;

    __nv_bfloat16 *gX, *gP1, *gP2, *gP3, *gP4, *gA;
    float *gRU;
    cudaGetSymbolAddress((void**)&gX,  g_X);
    cudaGetSymbolAddress((void**)&gP1, g_P1);
    cudaGetSymbolAddress((void**)&gP2, g_P2);
    cudaGetSymbolAddress((void**)&gP3, g_P3);
    cudaGetSymbolAddress((void**)&gP4, g_P4);
    cudaGetSymbolAddress((void**)&gA,  g_A);
    cudaGetSymbolAddress((void**)&gRU, g_RU);

    static bool attr_set = false;
    if (!attr_set) {
        cudaFuncSetAttribute(mma_gemm, cudaFuncAttributeMaxDynamicSharedMemorySize, SM_TOT);
        attr_set = true;
    }

    const dim3 ggrid(NN / NB, MROWS / MB);   // (8, 66)
    const int packBlocks = (MROWS * 256 + 255) / 256;
    const __nv_bfloat16* gA0 = gA;
    const __nv_bfloat16* gA1 = gA + (size_t)NN * KW;

    splitA_kernel<<<(2 * NN * 256 + 255) / 256, 256>>>(A0, A1, gA);

    // ---------- pass 1: ru gates ----------
    pack1_kernel<<<packBlocks, 256>>>(inputs, hx, gX);
    mma_gemm<<<ggrid, 256, SM_TOT>>>(gX,  gA0, nullptr, gP1, 0);
    mma_gemm<<<ggrid, 256, SM_TOT>>>(gP1, gA0, gX,      gP2, 1);
    mma_gemm<<<ggrid, 256, SM_TOT>>>(gX,  gA1, nullptr, gP3, 0);
    mma_gemm<<<ggrid, 256, SM_TOT>>>(gP3, gA1, gX,      gP4, 1);
    proj_kernel<<<dim3(8, 2, Bn), 256>>>(W_ru, b_ru, gX, gP1, gP2, gP3, gP4,
                                         nullptr, nullptr, gRU, 0);

    // ---------- pass 2: candidate + output ----------
    pack2_kernel<<<packBlocks, 256>>>(inputs, hx, gRU, gX);
    mma_gemm<<<ggrid, 256, SM_TOT>>>(gX,  gA0, nullptr, gP1, 0);
    mma_gemm<<<ggrid, 256, SM_TOT>>>(gP1, gA0, gX,      gP2, 1);
    mma_gemm<<<ggrid, 256, SM_TOT>>>(gX,  gA1, nullptr, gP3, 0);
    mma_gemm<<<ggrid, 256, SM_TOT>>>(gP3, gA1, gX,      gP4, 1);
    proj_kernel<<<dim3(8, 1, Bn), 256>>>(W_C, b_C, gX, gP1, gP2, gP3, gP4,
                                         gRU, hx, out, 1);
}

// round 4
// speedup vs baseline: 3.2091x; 1.3735x over previous
#include <cuda_runtime.h>
#include <cuda_bf16.h>
#include <math.h>
#include <stdint.h>

// Problem constants
#define Bn    128
#define HIDD  64
#define INDIM 2
#define CX    66
#define NN    1024
#define MROWS (Bn * CX)       // 8448
#define KW    2048            // hi|lo packed width per row

// ---------------- scratch (device globals) ----------------
__device__ __nv_bfloat16 g_X [MROWS * KW];
__device__ __nv_bfloat16 g_P1[MROWS * KW];
__device__ __nv_bfloat16 g_P2[MROWS * KW];
__device__ __nv_bfloat16 g_P3[MROWS * KW];
__device__ __nv_bfloat16 g_P4[MROWS * KW];
__device__ __nv_bfloat16 g_A [2 * NN * KW];          // A0,A1 split hi|lo
__device__ float         g_RU[Bn * 2 * HIDD * NN];   // sigmoid gates fp32
__device__ __nv_bfloat16 g_Wru[128 * 1024];          // W_ru split 3-seg
__device__ __nv_bfloat16 g_WC [64 * 1024];           // W_C split 3-seg

// ---------------- PTX helpers (base ISA only) ----------------
__device__ __forceinline__ uint32_t smem_u32(const void* p) {
    uint32_t a;
    asm("{ .reg .u64 t; cvta.to.shared.u64 t, %1; cvt.u32.u64 %0, t; }" : "=r"(a) : "l"(p));
    return a;
}
__device__ __forceinline__ void cp16(uint32_t dst, const void* src) {
    asm volatile("cp.async.cg.shared.global [%0], [%1], 16;" :: "r"(dst), "l"(src) : "memory");
}
__device__ __forceinline__ void ldm_x4(uint32_t* r, uint32_t a) {
    asm volatile("ldmatrix.sync.aligned.m8n8.x4.shared.b16 {%0,%1,%2,%3}, [%4];"
                 : "=r"(r[0]), "=r"(r[1]), "=r"(r[2]), "=r"(r[3]) : "r"(a));
}
__device__ __forceinline__ void ldm_x4t(uint32_t* r, uint32_t a) {
    asm volatile("ldmatrix.sync.aligned.m8n8.x4.trans.shared.b16 {%0,%1,%2,%3}, [%4];"
                 : "=r"(r[0]), "=r"(r[1]), "=r"(r[2]), "=r"(r[3]) : "r"(a));
}
__device__ __forceinline__ void mma16816(float* c, const uint32_t* a, const uint32_t* b) {
    asm volatile("mma.sync.aligned.m16n8k16.row.col.f32.bf16.bf16.f32 "
                 "{%0,%1,%2,%3},{%4,%5,%6,%7},{%8,%9},{%0,%1,%2,%3};"
                 : "+f"(c[0]), "+f"(c[1]), "+f"(c[2]), "+f"(c[3])
                 : "r"(a[0]), "r"(a[1]), "r"(a[2]), "r"(a[3]), "r"(b[0]), "r"(b[1]));
}

// ============================================================
// Big GEMM via HMMA, 3-stage cp.async pipeline, 1 barrier/iter.
// D[m,n] = sum over 3 segments Xseg[m,k]*Aseg[n,k]  (K=3072)
// Out(hi|lo bf16) = split( doBeta ? 2*D - X0 : D )
// CTA tile 128x128, 8 warps (4m x 2n), k-tile 64.
// ============================================================
#define MB 128
#define NT 48
#define STG_BYTES 32768            // (128+128)*64*2
#define SM_TOT (3 * STG_BYTES)     // 98304

__global__ void __launch_bounds__(256, 2)
mma_gemm(const __nv_bfloat16* __restrict__ Xin,
         const __nv_bfloat16* __restrict__ Ain,
         const __nv_bfloat16* __restrict__ X0,
         __nv_bfloat16* __restrict__ Out,
         int doBeta)
{
    extern __shared__ char smem[];
    const uint32_t sb = smem_u32(smem);
    const int tid  = threadIdx.x;
    const int lane = tid & 31;
    const int wid  = tid >> 5;
    const int wm   = wid & 3;
    const int wn   = wid >> 2;
    const int bm   = blockIdx.y * MB;
    const int bn   = blockIdx.x * MB;

    float acc[2][8][4];
#pragma unroll
    for (int t2 = 0; t2 < 2; t2++)
#pragma unroll
        for (int j = 0; j < 8; j++)
#pragma unroll
            for (int e = 0; e < 4; e++) acc[t2][j][e] = 0.0f;

    auto fill = [&](int t) {
        const int s    = t >> 4;
        const int kt   = (t & 15) * 64;
        const int xoff = (s == 1) ? 1024 : 0;
        const int aoff = (s == 2) ? 1024 : 0;
        const uint32_t sa = sb + (t % 3) * STG_BYTES;
        const uint32_t sB = sa + 16384;
#pragma unroll
        for (int j = 0; j < 4; j++) {
            const int u = tid + j * 256;
            const int row = u >> 3, ch = u & 7;
            cp16(sa + row * 128 + ((ch ^ (row & 7)) * 16),
                 Xin + (size_t)(bm + row) * KW + xoff + kt + ch * 8);
        }
#pragma unroll
        for (int j = 0; j < 4; j++) {
            const int u = tid + j * 256;
            const int row = u >> 3, ch = u & 7;
            cp16(sB + row * 128 + ((ch ^ (row & 7)) * 16),
                 Ain + (size_t)(bn + row) * KW + aoff + kt + ch * 8);
        }
        asm volatile("cp.async.commit_group;" ::: "memory");
    };

    const int arow_l = (lane & 15);
    const int ach_l  = (lane >> 4);
    const int bgrp   = lane >> 3;
    const int brow_l = (lane & 7) + ((bgrp >> 1) << 3);
    const int bch_l  = (bgrp & 1);

    fill(0);
    fill(1);

    for (int t = 0; t < NT; t++) {
        if (t < NT - 1) asm volatile("cp.async.wait_group 1;" ::: "memory");
        else            asm volatile("cp.async.wait_group 0;" ::: "memory");
        __syncthreads();
        if (t + 2 < NT) fill(t + 2);

        const uint32_t sa = sb + (t % 3) * STG_BYTES;
        const uint32_t sB = sa + 16384;
#pragma unroll
        for (int ks = 0; ks < 4; ks++) {
            uint32_t afr[2][4];
#pragma unroll
            for (int t2 = 0; t2 < 2; t2++) {
                const int row = wm * 32 + t2 * 16 + arow_l;
                const int ch  = 2 * ks + ach_l;
                ldm_x4(afr[t2], sa + row * 128 + ((ch ^ (row & 7)) * 16));
            }
            uint32_t bfr[4][4];
#pragma unroll
            for (int tn = 0; tn < 4; tn++) {
                const int row = wn * 64 + tn * 16 + brow_l;
                const int ch  = 2 * ks + bch_l;
                ldm_x4(bfr[tn], sB + row * 128 + ((ch ^ (row & 7)) * 16));
            }
#pragma unroll
            for (int t2 = 0; t2 < 2; t2++)
#pragma unroll
                for (int j = 0; j < 8; j++)
                    mma16816(acc[t2][j], afr[t2], &bfr[j >> 1][(j & 1) * 2]);
        }
    }

    // ---- epilogue ----
    const int g  = lane >> 2;
    const int c2 = (lane & 3) * 2;
#pragma unroll
    for (int t2 = 0; t2 < 2; t2++) {
#pragma unroll
        for (int j = 0; j < 8; j++) {
            const int col = bn + wn * 64 + j * 8 + c2;
#pragma unroll
            for (int half = 0; half < 2; half++) {
                const int row = bm + wm * 32 + t2 * 16 + g + half * 8;
                const size_t base = (size_t)row * KW + col;
                float v0 = acc[t2][j][half * 2 + 0];
                float v1 = acc[t2][j][half * 2 + 1];
                if (doBeta) {
                    union { uint32_t u; __nv_bfloat16 h[2]; } Hh, Hl;
                    Hh.u = *(const uint32_t*)(X0 + base);
                    Hl.u = *(const uint32_t*)(X0 + base + 1024);
                    v0 = 2.0f * v0 - (__bfloat162float(Hh.h[0]) + __bfloat162float(Hl.h[0]));
                    v1 = 2.0f * v1 - (__bfloat162float(Hh.h[1]) + __bfloat162float(Hl.h[1]));
                }
                union { uint32_t u; __nv_bfloat16 h[2]; } Oh, Ol;
                Oh.h[0] = __float2bfloat16(v0);
                Oh.h[1] = __float2bfloat16(v1);
                Ol.h[0] = __float2bfloat16(v0 - __bfloat162float(Oh.h[0]));
                Ol.h[1] = __float2bfloat16(v1 - __bfloat162float(Oh.h[1]));
                *(uint32_t*)(Out + base)        = Oh.u;
                *(uint32_t*)(Out + base + 1024) = Ol.u;
            }
        }
    }
}

// ============================================================
// Projection via HMMA. C^T tile [128 n][OTILE o] per CTA.
// K = 3 segs * 336 (330 real + 6 zero-pad) = 1008, k-tile 48.
// MODE 0: RU = sigmoid(W@H+b). MODE 1: out = u*hx+(1-u)*tanh(W@H+b).
// grid (8, Bn), 256 threads, 8 warps = 4(n) x 2(o).
// ============================================================
#define PKT 48
#define PNT 21
#define CSTR 132

template<int OTILE, int MODE>
__global__ void __launch_bounds__(256, 2)
proj_mma(const __nv_bfloat16* __restrict__ Wsp, const float* __restrict__ bias,
         const __nv_bfloat16* __restrict__ p0, const __nv_bfloat16* __restrict__ p1,
         const __nv_bfloat16* __restrict__ p2, const __nv_bfloat16* __restrict__ p3,
         const __nv_bfloat16* __restrict__ p4,
         const float* __restrict__ RU, const float* __restrict__ hx,
         float* __restrict__ outp)
{
    constexpr int HS_B   = PKT * 256;          // 12288
    constexpr int WS_B   = OTILE * 128;
    constexpr int STG    = HS_B + WS_B;
    constexpr int OW     = OTILE / 2;          // per-warp o tile
    constexpr int NJ     = OW / 8;             // o8 blocks per warp

    extern __shared__ char smem[];
    const uint32_t sb = smem_u32(smem);
    float* Cs = (float*)smem;

    const int tid  = threadIdx.x;
    const int lane = tid & 31;
    const int wid  = tid >> 5;
    const int wm   = wid & 3;
    const int wn   = wid >> 2;
    const int b    = blockIdx.y;
    const int bn0  = blockIdx.x * 128;

    float acc[2][NJ][4];
#pragma unroll
    for (int t2 = 0; t2 < 2; t2++)
#pragma unroll
        for (int j = 0; j < NJ; j++)
#pragma unroll
            for (int e = 0; e < 4; e++) acc[t2][j][e] = 0.0f;

    auto fill = [&](int t) {
        const int seg = t / 7;
        const int kt  = (t - seg * 7) * PKT;
        const int hoff = (seg == 1) ? 1024 : 0;
        const uint32_t hs = sb + (t & 1) * STG;
        const uint32_t ws = hs + HS_B;
        // H: 48 rows x 16 chunks = 768
#pragma unroll
        for (int j = 0; j < 3; j++) {
            const int u = tid + j * 256;
            const int r = u >> 4, ch = u & 15;
            int c = kt + r;
            if (c >= 330) c = 0;               // zero-padded rows: W side is 0
            const int p  = c / 66;
            const int cc = c - p * 66;
            const __nv_bfloat16* src = p0;
            if (p == 1) src = p1;
            else if (p == 2) src = p2;
            else if (p == 3) src = p3;
            else if (p == 4) src = p4;
            cp16(hs + r * 256 + ((ch ^ (r & 15)) << 4),
                 src + ((size_t)b * CX + cc) * KW + hoff + bn0 + ch * 8);
        }
        // W: OTILE rows x 6 chunks
#pragma unroll
        for (int j = 0; j < (OTILE * 6 + 255) / 256; j++) {
            const int u = tid + j * 256;
            if (u < OTILE * 6) {
                const int orow = u / 6, wc = u - orow * 6;
                cp16(ws + orow * 128 + ((wc ^ (orow & 7)) << 4),
                     Wsp + (size_t)orow * 1024 + seg * 336 + kt + wc * 8);
            }
        }
        asm volatile("cp.async.commit_group;" ::: "memory");
    };

    // A (H^T) via ldmatrix.trans from [k][n]
    const int krow_l = (lane & 7) + ((lane >> 4) << 3);
    const int m8sel  = (lane >> 3) & 1;
    // B (W) non-trans from [o][k]
    const int bgrp   = lane >> 3;
    const int brow_l = (lane & 7) + ((bgrp >> 1) << 3);
    const int bch_l  = (bgrp & 1);

    fill(0);
    for (int t = 0; t < PNT; t++) {
        if (t + 1 < PNT) {
            fill(t + 1);
            asm volatile("cp.async.wait_group 1;" ::: "memory");
        } else {
            asm volatile("cp.async.wait_group 0;" ::: "memory");
        }
        __syncthreads();

        const uint32_t hs = sb + (t & 1) * STG;
        const uint32_t ws = hs + HS_B;
#pragma unroll
        for (int ks = 0; ks < 3; ks++) {
            uint32_t afr[2][4];
#pragma unroll
            for (int t2 = 0; t2 < 2; t2++) {
                const int kr  = ks * 16 + krow_l;
                const int chm = (wm * 4) + (t2 * 2) + m8sel;   // chunk of n
                ldm_x4t(afr[t2], hs + kr * 256 + ((chm ^ (kr & 15)) << 4));
            }
            uint32_t bfr[NJ / 2 > 0 ? NJ / 2 : 1][4];
#pragma unroll
            for (int tn = 0; tn < NJ / 2; tn++) {
                const int row = wn * OW + tn * 16 + brow_l;
                const int ch  = 2 * ks + bch_l;
                ldm_x4(bfr[tn], ws + row * 128 + ((ch ^ (row & 7)) << 4));
            }
#pragma unroll
            for (int t2 = 0; t2 < 2; t2++)
#pragma unroll
                for (int j = 0; j < NJ; j++)
                    mma16816(acc[t2][j], afr[t2], &bfr[j >> 1][(j & 1) * 2]);
        }
        __syncthreads();
    }

    // ---- epilogue: transpose through smem, coalesced stores ----
    __syncthreads();
    const int g  = lane >> 2;
    const int c2 = (lane & 3) * 2;
#pragma unroll
    for (int t2 = 0; t2 < 2; t2++)
#pragma unroll
        for (int j = 0; j < NJ; j++)
#pragma unroll
            for (int e = 0; e < 4; e++) {
                const int n = wm * 32 + t2 * 16 + g + (e >> 1) * 8;
                const int o = wn * OW + j * 8 + c2 + (e & 1);
                Cs[o * CSTR + n] = acc[t2][j][e];
            }
    __syncthreads();

    for (int o = wid; o < OTILE; o += 8) {
        const float bv = bias[o];
        const int n = lane * 4;
        float4 v = *(float4*)&Cs[o * CSTR + n];
        if (MODE == 0) {
            v.x = 1.0f / (1.0f + expf(-(v.x + bv)));
            v.y = 1.0f / (1.0f + expf(-(v.y + bv)));
            v.z = 1.0f / (1.0f + expf(-(v.z + bv)));
            v.w = 1.0f / (1.0f + expf(-(v.w + bv)));
            *(float4*)(outp + ((size_t)b * 128 + o) * NN + bn0 + n) = v;
        } else {
            const float4 u4 = *(const float4*)(RU + ((size_t)b * 128 + 64 + o) * NN + bn0 + n);
            const float4 h4 = *(const float4*)(hx + ((size_t)b * HIDD + o) * NN + bn0 + n);
            float4 r;
            r.x = u4.x * h4.x + (1.0f - u4.x) * tanhf(v.x + bv);
            r.y = u4.y * h4.y + (1.0f - u4.y) * tanhf(v.y + bv);
            r.z = u4.z * h4.z + (1.0f - u4.z) * tanhf(v.z + bv);
            r.w = u4.w * h4.w + (1.0f - u4.w) * tanhf(v.w + bv);
            *(float4*)(outp + ((size_t)b * HIDD + o) * NN + bn0 + n) = r;
        }
    }
}

// ============================================================
// split / pack kernels
// ============================================================
__device__ __forceinline__ void split4(const float4 v, __nv_bfloat16* hi4, __nv_bfloat16* lo4) {
    const float f[4] = { v.x, v.y, v.z, v.w };
#pragma unroll
    for (int e = 0; e < 4; e++) {
        const __nv_bfloat16 h = __float2bfloat16(f[e]);
        hi4[e] = h;
        lo4[e] = __float2bfloat16(f[e] - __bfloat162float(h));
    }
}

__global__ void splitA_kernel(const float* __restrict__ A0, const float* __restrict__ A1,
                              __nv_bfloat16* __restrict__ Aout)
{
    const int idx = blockIdx.x * blockDim.x + threadIdx.x;
    if (idx >= 2 * NN * 256) return;
    const int adj = idx >> 18;
    const int r   = idx & ((1 << 18) - 1);
    const int row = r >> 8;
    const int n4  = r & 255;
    const float4 v = ((const float4*)(adj ? A1 : A0))[(size_t)row * 256 + n4];
    union { uint2 u; __nv_bfloat16 h[4]; } H, L;
    split4(v, H.h, L.h);
    __nv_bfloat16* dst = Aout + (size_t)adj * NN * KW + (size_t)row * KW + n4 * 4;
    *(uint2*)(dst)        = H.u;
    *(uint2*)(dst + 1024) = L.u;
}

// W split: rows = 192 (128 ru + 64 C), cols 336 padded; 3 segments each.
__global__ void splitW_kernel(const float* __restrict__ W_ru, const float* __restrict__ W_C,
                              __nv_bfloat16* __restrict__ Wru, __nv_bfloat16* __restrict__ WC)
{
    const int idx = blockIdx.x * blockDim.x + threadIdx.x;   // 192*336
    if (idx >= 192 * 336) return;
    const int o = idx / 336;
    const int c = idx - o * 336;
    float w = 0.0f;
    if (c < 330) w = (o < 128) ? W_ru[(size_t)o * 330 + c] : W_C[(size_t)(o - 128) * 330 + c];
    const __nv_bfloat16 hi = __float2bfloat16(w);
    const __nv_bfloat16 lo = __float2bfloat16(w - __bfloat162float(hi));
    __nv_bfloat16* dst = (o < 128) ? (Wru + (size_t)o * 1024) : (WC + (size_t)(o - 128) * 1024);
    dst[c]       = hi;
    dst[336 + c] = hi;
    dst[672 + c] = lo;
}

__global__ void pack1_kernel(const float* __restrict__ inputs, const float* __restrict__ hx,
                             __nv_bfloat16* __restrict__ X)
{
    const int idx = blockIdx.x * blockDim.x + threadIdx.x;
    if (idx >= MROWS * 256) return;
    const int n4 = idx & 255;
    const int t  = idx >> 8;
    const int c  = t % CX;
    const int b  = t / CX;
    float4 v;
    if (c < INDIM)
        v = ((const float4*)inputs)[((size_t)b * INDIM + c) * 256 + n4];
    else
        v = ((const float4*)hx)[((size_t)b * HIDD + (c - INDIM)) * 256 + n4];
    union { uint2 u; __nv_bfloat16 h[4]; } H, L;
    split4(v, H.h, L.h);
    __nv_bfloat16* dst = X + (size_t)t * KW + n4 * 4;
    *(uint2*)(dst)        = H.u;
    *(uint2*)(dst + 1024) = L.u;
}

__global__ void pack2_kernel(const float* __restrict__ inputs, const float* __restrict__ hx,
                             const float* __restrict__ RU, __nv_bfloat16* __restrict__ X)
{
    const int idx = blockIdx.x * blockDim.x + threadIdx.x;
    if (idx >= MROWS * 256) return;
    const int n4 = idx & 255;
    const int t  = idx >> 8;
    const int c  = t % CX;
    const int b  = t / CX;
    float4 v;
    if (c < INDIM) {
        v = ((const float4*)inputs)[((size_t)b * INDIM + c) * 256 + n4];
    } else {
        const int cc = c - INDIM;
        const float4 r = ((const float4*)RU)[((size_t)b * 128 + cc) * 256 + n4];
        const float4 h = ((const float4*)hx)[((size_t)b * HIDD + cc) * 256 + n4];
        v.x = r.x * h.x; v.y = r.y * h.y; v.z = r.z * h.z; v.w = r.w * h.w;
    }
    union { uint2 u; __nv_bfloat16 h[4]; } H, L;
    split4(v, H.h, L.h);
    __nv_bfloat16* dst = X + (size_t)t * KW + n4 * 4;
    *(uint2*)(dst)        = H.u;
    *(uint2*)(dst + 1024) = L.u;
}

// ============================================================
extern "C" void kernel_launch(void* const* d_in, const int* in_sizes, int n_in,
                              void* d_out, int out_size)
{
    const float* inputs = (const float*)d_in[0];
    const float* hx     = (const float*)d_in[1];
    const float* A0     = (const float*)d_in[2];
    const float* A1     = (const float*)d_in[3];
    const float* W_ru   = (const float*)d_in[4];
    const float* b_ru   = (const float*)d_in[5];
    const float* W_C    = (const float*)d_in[6];
    const float* b_C    = (const float*)d_in[7];
    float* out = (float*)d_out;

    __nv_bfloat16 *gX, *gP1, *gP2, *gP3, *gP4, *gA, *gWru, *gWC;
    float *gRU;
    cudaGetSymbolAddress((void**)&gX,  g_X);
    cudaGetSymbolAddress((void**)&gP1, g_P1);
    cudaGetSymbolAddress((void**)&gP2, g_P2);
    cudaGetSymbolAddress((void**)&gP3, g_P3);
    cudaGetSymbolAddress((void**)&gP4, g_P4);
    cudaGetSymbolAddress((void**)&gA,  g_A);
    cudaGetSymbolAddress((void**)&gRU, g_RU);
    cudaGetSymbolAddress((void**)&gWru, g_Wru);
    cudaGetSymbolAddress((void**)&gWC,  g_WC);

    static bool attr_set = false;
    if (!attr_set) {
        cudaFuncSetAttribute(mma_gemm, cudaFuncAttributeMaxDynamicSharedMemorySize, SM_TOT);
        cudaFuncSetAttribute(proj_mma<128, 0>, cudaFuncAttributeMaxDynamicSharedMemorySize, 128 * CSTR * 4);
        cudaFuncSetAttribute(proj_mma<64, 1>,  cudaFuncAttributeMaxDynamicSharedMemorySize, 64 * 1024);
        attr_set = true;
    }
    const int smem0 = 128 * CSTR * 4;                 // max(57344 pipe, 67584 Cs)
    const int smem1 = 2 * (PKT * 256 + 64 * 128) > 64 * CSTR * 4
                    ? 2 * (PKT * 256 + 64 * 128) : 64 * CSTR * 4;

    const dim3 ggrid(NN / MB, MROWS / MB);   // (8, 66)
    const int packBlocks = (MROWS * 256 + 255) / 256;
    const __nv_bfloat16* gA0 = gA;
    const __nv_bfloat16* gA1 = gA + (size_t)NN * KW;

    splitA_kernel<<<(2 * NN * 256 + 255) / 256, 256>>>(A0, A1, gA);
    splitW_kernel<<<(192 * 336 + 255) / 256, 256>>>(W_ru, W_C, gWru, gWC);

    // ---------- pass 1: ru gates ----------
    pack1_kernel<<<packBlocks, 256>>>(inputs, hx, gX);
    mma_gemm<<<ggrid, 256, SM_TOT>>>(gX,  gA0, nullptr, gP1, 0);
    mma_gemm<<<ggrid, 256, SM_TOT>>>(gP1, gA0, gX,      gP2, 1);
    mma_gemm<<<ggrid, 256, SM_TOT>>>(gX,  gA1, nullptr, gP3, 0);
    mma_gemm<<<ggrid, 256, SM_TOT>>>(gP3, gA1, gX,      gP4, 1);
    proj_mma<128, 0><<<dim3(8, Bn), 256, smem0>>>(gWru, b_ru, gX, gP1, gP2, gP3, gP4,
                                                  nullptr, nullptr, gRU);

    // ---------- pass 2: candidate + output ----------
    pack2_kernel<<<packBlocks, 256>>>(inputs, hx, gRU, gX);
    mma_gemm<<<ggrid, 256, SM_TOT>>>(gX,  gA0, nullptr, gP1, 0);
    mma_gemm<<<ggrid, 256, SM_TOT>>>(gP1, gA0, gX,      gP2, 1);
    mma_gemm<<<ggrid, 256, SM_TOT>>>(gX,  gA1, nullptr, gP3, 0);
    mma_gemm<<<ggrid, 256, SM_TOT>>>(gP3, gA1, gX,      gP4, 1);
    proj_mma<64, 1><<<dim3(8, Bn), 256, smem1>>>(gWC, b_C, gX, gP1, gP2, gP3, gP4,
                                                 gRU, hx, out);
}